// round 9
// baseline (speedup 1.0000x reference)
#include <cuda_runtime.h>
#include <cuda_bf16.h>
#include <cstdint>

// Shapes fixed by reference setup_inputs():
//   z_e: (B=64, D=64, H=32, W=32) fp32, embedding: (K=1024, D=64) fp32
// Output layout (fp32 concat):
//   [0, 4194304)   z_q (B,D,H,W)
//   [4194304]      commitment_loss
//   [4194305,...)  indices (B,H,W) as float  (65536)
//   [4259841]      codebook_usage

#define NVEC   65536
#define DDIM   64
#define KCODES 1024
#define ZQ_ELEMS 4194304
#define LOSS_OFF 4194304
#define IDX_OFF  4194305
#define USAGE_OFF 4259841

typedef unsigned long long u64;

// Scratch (no device allocation allowed)
__device__ float g_c[KCODES];        // ||e_k||^2
__device__ int   g_used[KCODES];     // usage flags
__device__ float g_partial[512];     // per-block loss partials (main grid = 512)
__device__ unsigned int g_done_ctr;  // last-block-done counter

#define FMA2(acc, a, b) \
    asm("fma.rn.f32x2 %0, %1, %2, %0;" : "+l"(acc) : "l"(a), "l"(b))
#define PACK_DUP(dst, f) \
    asm("mov.b64 %0, {%1, %1};" : "=l"(dst) : "f"(f))
#define UNPACK2(lo, hi, src) \
    asm("mov.b64 {%0, %1}, %2;" : "=f"(lo), "=f"(hi) : "l"(src))

// ---------------------------------------------------------------------------
// Kernel A: per-code squared norms + zero usage flags + reset counter. <<<4,256>>>
// ---------------------------------------------------------------------------
__global__ void vq_prep(const float* __restrict__ emb) {
    int t = blockIdx.x * 256 + threadIdx.x;   // 0..1023 == code id
    const float4* ep = (const float4*)(emb + (size_t)t * DDIM);
    float s = 0.f;
#pragma unroll
    for (int i = 0; i < DDIM / 4; i++) {
        float4 v = ep[i];
        s = fmaf(v.x, v.x, s); s = fmaf(v.y, v.y, s);
        s = fmaf(v.z, v.z, s); s = fmaf(v.w, v.w, s);
    }
    g_c[t] = s;
    g_used[t] = 0;
    if (t == 0) g_done_ctr = 0u;
}

// ---------------------------------------------------------------------------
// Kernel B: fused GEMM(argmax) + full epilogue.
// grid = 512 blocks (128 rows each), 256 threads.
// Inner product via packed fma.rn.f32x2: 8x4 f32x2 accumulators = 8x8 scalars.
// After argmax: gather codes into smem, write z_q / indices / usage, loss
// partial; last finished block reduces loss + usage.
// ---------------------------------------------------------------------------
#define ES 132   // padded Es row stride (floats); d*ES*4 = 528d bytes (16B mult)
#define SMEM_FLOATS (64*128 + 64*ES + 128 + 128)

__global__ __launch_bounds__(256, 2)
void vq_main(const float* __restrict__ ze, const float* __restrict__ emb,
             float* __restrict__ out) {
    extern __shared__ float sm[];
    float* Xs    = sm;                  // [64][128]
    float* Es    = sm + 64 * 128;       // [64][ES]  (reused as gathered codes)
    float* cs    = Es + 64 * ES;        // [128]
    int*   s_idx = (int*)(cs + 128);    // [128]

    const int tid = threadIdx.x;
    const int tc  = tid & 15;           // column group (8 codes)
    const int tr  = tid >> 4;           // row group (8 vectors)
    const int n0  = blockIdx.x * 128;
    const int b   = n0 >> 10;           // 128 | 1024 -> tile inside one b
    const int hw0 = n0 & 1023;

    // ---- Load X tile: Xs[d][n] = z_e[b, d, hw0+n] (contiguous along n) ----
#pragma unroll
    for (int r = 0; r < 8; r++) {
        int q  = tid + r * 256;
        int d  = q >> 5;
        int c4 = q & 31;
        float4 v = ((const float4*)(ze + (size_t)b * 65536 + (size_t)d * 1024 + hw0))[c4];
        *(float4*)&Xs[d * 128 + c4 * 4] = v;
    }

    float bestv[8];
    int   besti[8];
#pragma unroll
    for (int i = 0; i < 8; i++) { bestv[i] = -3.4e38f; besti[i] = 0; }

    for (int kt = 0; kt < 8; kt++) {
        const int k0 = kt * 128;
        __syncthreads();
        // Load E tile transposed: Es[d][kk] = emb[k0+kk][d]
#pragma unroll
        for (int r = 0; r < 8; r++) {
            int q  = tid + r * 256;
            int kk = q >> 4;
            int d4 = q & 15;
            float4 v = ((const float4*)(emb + (size_t)(k0 + kk) * DDIM))[d4];
            Es[(d4 * 4 + 0) * ES + kk] = v.x;
            Es[(d4 * 4 + 1) * ES + kk] = v.y;
            Es[(d4 * 4 + 2) * ES + kk] = v.z;
            Es[(d4 * 4 + 3) * ES + kk] = v.w;
        }
        if (tid < 128) cs[tid] = g_c[k0 + tid];
        __syncthreads();

        // 8x4 packed f32x2 accumulators covering an 8x8 scalar micro-tile
        u64 acc[8][4];
#pragma unroll
        for (int i = 0; i < 8; i++)
#pragma unroll
            for (int j = 0; j < 4; j++) acc[i][j] = 0ULL;

#pragma unroll 4
        for (int d = 0; d < DDIM; d++) {
            float4 xa = *(const float4*)&Xs[d * 128 + tr * 8];
            float4 xb = *(const float4*)&Xs[d * 128 + tr * 8 + 4];
            ulonglong2 ea = *(const ulonglong2*)&Es[d * ES + tc * 8];
            ulonglong2 eb = *(const ulonglong2*)&Es[d * ES + tc * 8 + 4];
            u64 ep[4] = {ea.x, ea.y, eb.x, eb.y};
            float xv[8] = {xa.x, xa.y, xa.z, xa.w, xb.x, xb.y, xb.z, xb.w};
            u64 xd[8];
#pragma unroll
            for (int i = 0; i < 8; i++) PACK_DUP(xd[i], xv[i]);
#pragma unroll
            for (int i = 0; i < 8; i++) {
                FMA2(acc[i][0], xd[i], ep[0]);
                FMA2(acc[i][1], xd[i], ep[1]);
                FMA2(acc[i][2], xd[i], ep[2]);
                FMA2(acc[i][3], xd[i], ep[3]);
            }
        }

        // Fold tile scores (score = 2*dot - ||e||^2; max == argmin distance;
        // ascending k + strict > keeps the lowest index on ties)
#pragma unroll
        for (int j2 = 0; j2 < 4; j2++) {
            int   kA = k0 + tc * 8 + 2 * j2;
            float cA = cs[tc * 8 + 2 * j2];
            float cB = cs[tc * 8 + 2 * j2 + 1];
#pragma unroll
            for (int i = 0; i < 8; i++) {
                float lo, hi;
                UNPACK2(lo, hi, acc[i][j2]);
                float sA = fmaf(2.f, lo, -cA);
                float sB = fmaf(2.f, hi, -cB);
                if (sA > bestv[i]) { bestv[i] = sA; besti[i] = kA; }
                if (sB > bestv[i]) { bestv[i] = sB; besti[i] = kA + 1; }
            }
        }
    }

    // ---- Reduce argmax across the 16 lanes sharing a row group ----
#pragma unroll
    for (int i = 0; i < 8; i++) {
        float v  = bestv[i];
        int   ix = besti[i];
#pragma unroll
        for (int off = 8; off; off >>= 1) {
            float ov = __shfl_xor_sync(0xffffffffu, v, off);
            int   oi = __shfl_xor_sync(0xffffffffu, ix, off);
            if (ov > v || (ov == v && oi < ix)) { v = ov; ix = oi; }
        }
        if (tc == 0) s_idx[tr * 8 + i] = ix;
    }
    __syncthreads();

    // ---- Epilogue: gather selected code rows into Es (transposed) ----
    // Eg[d][n] = emb[s_idx[n]][d], pitch ES (reuses Es storage exactly).
#pragma unroll
    for (int r = 0; r < 8; r++) {
        int q  = tid + r * 256;       // 2048 slots = 128 n x 16 chunks
        int nl = q >> 4;
        int c4 = q & 15;
        int k  = s_idx[nl];
        float4 v = ((const float4*)(emb + (size_t)k * DDIM))[c4];
        Es[(c4 * 4 + 0) * ES + nl] = v.x;
        Es[(c4 * 4 + 1) * ES + nl] = v.y;
        Es[(c4 * 4 + 2) * ES + nl] = v.z;
        Es[(c4 * 4 + 3) * ES + nl] = v.w;
    }
    if (tid < 128) {
        out[IDX_OFF + n0 + tid] = (float)s_idx[tid];
        g_used[s_idx[tid]] = 1;
    }
    __syncthreads();

    // ---- z_q writes (coalesced) + loss partial, using Xs still in smem ----
    float lsum = 0.f;
    const size_t baseo = (size_t)b * 65536 + hw0;
#pragma unroll
    for (int it = 0; it < 32; it++) {
        int t2 = tid + it * 256;      // 8192 slots = 64 d x 128 n
        int d  = t2 >> 7;
        int nl = t2 & 127;
        float e = Es[d * ES + nl];
        float x = Xs[d * 128 + nl];
        float df = x - e;
        lsum = fmaf(df, df, lsum);
        out[baseo + (size_t)d * 1024 + nl] = e;
    }

    __shared__ float red[256];
    __shared__ unsigned int s_old;
    red[tid] = lsum;
    __syncthreads();
#pragma unroll
    for (int s = 128; s; s >>= 1) {
        if (tid < s) red[tid] += red[tid + s];
        __syncthreads();
    }
    if (tid == 0) g_partial[blockIdx.x] = red[0];

    // ---- Last-block final reduction (deterministic) ----
    __threadfence();
    __syncthreads();
    if (tid == 0) s_old = atomicAdd(&g_done_ctr, 1u);
    __syncthreads();
    if (s_old == 511u) {
        __threadfence();
        volatile float* gp = g_partial;
        volatile int*   gu = g_used;
        float ls = gp[tid] + gp[tid + 256];
        int   us = gu[tid * 4] + gu[tid * 4 + 1] + gu[tid * 4 + 2] + gu[tid * 4 + 3];
        __shared__ int redi[256];
        red[tid]  = ls;
        redi[tid] = us;
        __syncthreads();
#pragma unroll
        for (int s = 128; s; s >>= 1) {
            if (tid < s) { red[tid] += red[tid + s]; redi[tid] += redi[tid + s]; }
            __syncthreads();
        }
        if (tid == 0) {
            out[LOSS_OFF]  = red[0] / (float)ZQ_ELEMS;
            out[USAGE_OFF] = (float)redi[0] / (float)KCODES;
        }
    }
}

// ---------------------------------------------------------------------------
extern "C" void kernel_launch(void* const* d_in, const int* in_sizes, int n_in,
                              void* d_out, int out_size) {
    const float* ze  = (const float*)d_in[0];
    const float* emb = (const float*)d_in[1];
    float* out = (float*)d_out;

    const int smem_bytes = SMEM_FLOATS * sizeof(float);
    cudaFuncSetAttribute(vq_main, cudaFuncAttributeMaxDynamicSharedMemorySize,
                         smem_bytes);

    vq_prep<<<4, 256>>>(emb);
    vq_main<<<512, 256, smem_bytes>>>(ze, emb, out);
}

// round 10
// speedup vs baseline: 1.0010x; 1.0010x over previous
#include <cuda_runtime.h>
#include <cuda_bf16.h>
#include <cstdint>

// Shapes fixed by reference setup_inputs():
//   z_e: (B=64, D=64, H=32, W=32) fp32, embedding: (K=1024, D=64) fp32
// Output layout (fp32 concat):
//   [0, 4194304)   z_q (B,D,H,W)
//   [4194304]      commitment_loss
//   [4194305,...)  indices (B,H,W) as float  (65536)
//   [4259841]      codebook_usage

#define NVEC   65536
#define DDIM   64
#define KCODES 1024
#define ZQ_ELEMS 4194304
#define LOSS_OFF 4194304
#define IDX_OFF  4194305
#define USAGE_OFF 4259841

typedef unsigned long long u64;

// Scratch (no device allocation allowed)
__device__ float g_c[KCODES];        // ||e_k||^2
__device__ int   g_used[KCODES];     // usage flags
__device__ float g_partial[512];     // per-block loss partials (main grid = 512)
__device__ unsigned int g_done_ctr;  // last-block-done counter

#define FMA2(acc, a, b) \
    asm("fma.rn.f32x2 %0, %1, %2, %0;" : "+l"(acc) : "l"(a), "l"(b))
#define PACK_DUP(dst, f) \
    asm("mov.b64 %0, {%1, %1};" : "=l"(dst) : "f"(f))
#define UNPACK2(lo, hi, src) \
    asm("mov.b64 {%0, %1}, %2;" : "=f"(lo), "=f"(hi) : "l"(src))

// ---------------------------------------------------------------------------
// Kernel A: per-code squared norms + zero usage flags + reset counter. <<<4,256>>>
// ---------------------------------------------------------------------------
__global__ void vq_prep(const float* __restrict__ emb) {
    int t = blockIdx.x * 256 + threadIdx.x;   // 0..1023 == code id
    const float4* ep = (const float4*)(emb + (size_t)t * DDIM);
    float s = 0.f;
#pragma unroll
    for (int i = 0; i < DDIM / 4; i++) {
        float4 v = ep[i];
        s = fmaf(v.x, v.x, s); s = fmaf(v.y, v.y, s);
        s = fmaf(v.z, v.z, s); s = fmaf(v.w, v.w, s);
    }
    g_c[t] = s;
    g_used[t] = 0;
    if (t == 0) g_done_ctr = 0u;
}

// ---------------------------------------------------------------------------
// Kernel B: fused GEMM(argmax) + full epilogue.
// grid = 512 blocks (128 rows each), 256 threads.
// Inner product via packed fma.rn.f32x2: 8x4 f32x2 accumulators = 8x8 scalars.
// After argmax: gather codes into smem, write z_q / indices / usage, loss
// partial; last finished block reduces loss + usage.
// ---------------------------------------------------------------------------
#define ES 132   // padded Es row stride (floats); d*ES*4 = 528d bytes (16B mult)
#define SMEM_FLOATS (64*128 + 64*ES + 128 + 128)

__global__ __launch_bounds__(256, 2)
void vq_main(const float* __restrict__ ze, const float* __restrict__ emb,
             float* __restrict__ out) {
    extern __shared__ float sm[];
    float* Xs    = sm;                  // [64][128]
    float* Es    = sm + 64 * 128;       // [64][ES]  (reused as gathered codes)
    float* cs    = Es + 64 * ES;        // [128]
    int*   s_idx = (int*)(cs + 128);    // [128]

    const int tid = threadIdx.x;
    const int tc  = tid & 15;           // column group (8 codes)
    const int tr  = tid >> 4;           // row group (8 vectors)
    const int n0  = blockIdx.x * 128;
    const int b   = n0 >> 10;           // 128 | 1024 -> tile inside one b
    const int hw0 = n0 & 1023;

    // ---- Load X tile: Xs[d][n] = z_e[b, d, hw0+n] (contiguous along n) ----
#pragma unroll
    for (int r = 0; r < 8; r++) {
        int q  = tid + r * 256;
        int d  = q >> 5;
        int c4 = q & 31;
        float4 v = ((const float4*)(ze + (size_t)b * 65536 + (size_t)d * 1024 + hw0))[c4];
        *(float4*)&Xs[d * 128 + c4 * 4] = v;
    }

    float bestv[8];
    int   besti[8];
#pragma unroll
    for (int i = 0; i < 8; i++) { bestv[i] = -3.4e38f; besti[i] = 0; }

    for (int kt = 0; kt < 8; kt++) {
        const int k0 = kt * 128;
        __syncthreads();
        // Load E tile transposed: Es[d][kk] = emb[k0+kk][d]
#pragma unroll
        for (int r = 0; r < 8; r++) {
            int q  = tid + r * 256;
            int kk = q >> 4;
            int d4 = q & 15;
            float4 v = ((const float4*)(emb + (size_t)(k0 + kk) * DDIM))[d4];
            Es[(d4 * 4 + 0) * ES + kk] = v.x;
            Es[(d4 * 4 + 1) * ES + kk] = v.y;
            Es[(d4 * 4 + 2) * ES + kk] = v.z;
            Es[(d4 * 4 + 3) * ES + kk] = v.w;
        }
        if (tid < 128) cs[tid] = g_c[k0 + tid];
        __syncthreads();

        // 8x4 packed f32x2 accumulators covering an 8x8 scalar micro-tile
        u64 acc[8][4];
#pragma unroll
        for (int i = 0; i < 8; i++)
#pragma unroll
            for (int j = 0; j < 4; j++) acc[i][j] = 0ULL;

#pragma unroll 4
        for (int d = 0; d < DDIM; d++) {
            float4 xa = *(const float4*)&Xs[d * 128 + tr * 8];
            float4 xb = *(const float4*)&Xs[d * 128 + tr * 8 + 4];
            ulonglong2 ea = *(const ulonglong2*)&Es[d * ES + tc * 8];
            ulonglong2 eb = *(const ulonglong2*)&Es[d * ES + tc * 8 + 4];
            u64 ep[4] = {ea.x, ea.y, eb.x, eb.y};
            float xv[8] = {xa.x, xa.y, xa.z, xa.w, xb.x, xb.y, xb.z, xb.w};
            u64 xd[8];
#pragma unroll
            for (int i = 0; i < 8; i++) PACK_DUP(xd[i], xv[i]);
#pragma unroll
            for (int i = 0; i < 8; i++) {
                FMA2(acc[i][0], xd[i], ep[0]);
                FMA2(acc[i][1], xd[i], ep[1]);
                FMA2(acc[i][2], xd[i], ep[2]);
                FMA2(acc[i][3], xd[i], ep[3]);
            }
        }

        // Fold tile scores (score = 2*dot - ||e||^2; max == argmin distance;
        // ascending k + strict > keeps the lowest index on ties)
#pragma unroll
        for (int j2 = 0; j2 < 4; j2++) {
            int   kA = k0 + tc * 8 + 2 * j2;
            float cA = cs[tc * 8 + 2 * j2];
            float cB = cs[tc * 8 + 2 * j2 + 1];
#pragma unroll
            for (int i = 0; i < 8; i++) {
                float lo, hi;
                UNPACK2(lo, hi, acc[i][j2]);
                float sA = fmaf(2.f, lo, -cA);
                float sB = fmaf(2.f, hi, -cB);
                if (sA > bestv[i]) { bestv[i] = sA; besti[i] = kA; }
                if (sB > bestv[i]) { bestv[i] = sB; besti[i] = kA + 1; }
            }
        }
    }

    // ---- Reduce argmax across the 16 lanes sharing a row group ----
#pragma unroll
    for (int i = 0; i < 8; i++) {
        float v  = bestv[i];
        int   ix = besti[i];
#pragma unroll
        for (int off = 8; off; off >>= 1) {
            float ov = __shfl_xor_sync(0xffffffffu, v, off);
            int   oi = __shfl_xor_sync(0xffffffffu, ix, off);
            if (ov > v || (ov == v && oi < ix)) { v = ov; ix = oi; }
        }
        if (tc == 0) s_idx[tr * 8 + i] = ix;
    }
    __syncthreads();

    // ---- Epilogue: gather selected code rows into Es (transposed) ----
    // Eg[d][n] = emb[s_idx[n]][d], pitch ES (reuses Es storage exactly).
#pragma unroll
    for (int r = 0; r < 8; r++) {
        int q  = tid + r * 256;       // 2048 slots = 128 n x 16 chunks
        int nl = q >> 4;
        int c4 = q & 15;
        int k  = s_idx[nl];
        float4 v = ((const float4*)(emb + (size_t)k * DDIM))[c4];
        Es[(c4 * 4 + 0) * ES + nl] = v.x;
        Es[(c4 * 4 + 1) * ES + nl] = v.y;
        Es[(c4 * 4 + 2) * ES + nl] = v.z;
        Es[(c4 * 4 + 3) * ES + nl] = v.w;
    }
    if (tid < 128) {
        out[IDX_OFF + n0 + tid] = (float)s_idx[tid];
        g_used[s_idx[tid]] = 1;
    }
    __syncthreads();

    // ---- z_q writes (coalesced) + loss partial, using Xs still in smem ----
    float lsum = 0.f;
    const size_t baseo = (size_t)b * 65536 + hw0;
#pragma unroll
    for (int it = 0; it < 32; it++) {
        int t2 = tid + it * 256;      // 8192 slots = 64 d x 128 n
        int d  = t2 >> 7;
        int nl = t2 & 127;
        float e = Es[d * ES + nl];
        float x = Xs[d * 128 + nl];
        float df = x - e;
        lsum = fmaf(df, df, lsum);
        out[baseo + (size_t)d * 1024 + nl] = e;
    }

    __shared__ float red[256];
    __shared__ unsigned int s_old;
    red[tid] = lsum;
    __syncthreads();
#pragma unroll
    for (int s = 128; s; s >>= 1) {
        if (tid < s) red[tid] += red[tid + s];
        __syncthreads();
    }
    if (tid == 0) g_partial[blockIdx.x] = red[0];

    // ---- Last-block final reduction (deterministic) ----
    __threadfence();
    __syncthreads();
    if (tid == 0) s_old = atomicAdd(&g_done_ctr, 1u);
    __syncthreads();
    if (s_old == 511u) {
        __threadfence();
        volatile float* gp = g_partial;
        volatile int*   gu = g_used;
        float ls = gp[tid] + gp[tid + 256];
        int   us = gu[tid * 4] + gu[tid * 4 + 1] + gu[tid * 4 + 2] + gu[tid * 4 + 3];
        __shared__ int redi[256];
        red[tid]  = ls;
        redi[tid] = us;
        __syncthreads();
#pragma unroll
        for (int s = 128; s; s >>= 1) {
            if (tid < s) { red[tid] += red[tid + s]; redi[tid] += redi[tid + s]; }
            __syncthreads();
        }
        if (tid == 0) {
            out[LOSS_OFF]  = red[0] / (float)ZQ_ELEMS;
            out[USAGE_OFF] = (float)redi[0] / (float)KCODES;
        }
    }
}

// ---------------------------------------------------------------------------
extern "C" void kernel_launch(void* const* d_in, const int* in_sizes, int n_in,
                              void* d_out, int out_size) {
    const float* ze  = (const float*)d_in[0];
    const float* emb = (const float*)d_in[1];
    float* out = (float*)d_out;

    const int smem_bytes = SMEM_FLOATS * sizeof(float);
    cudaFuncSetAttribute(vq_main, cudaFuncAttributeMaxDynamicSharedMemorySize,
                         smem_bytes);

    vq_prep<<<4, 256>>>(emb);
    vq_main<<<512, 256, smem_bytes>>>(ze, emb, out);
}